// round 1
// baseline (speedup 1.0000x reference)
#include <cuda_runtime.h>
#include <math.h>

#define NN 100000
#define CC 128
#define EE 600000
#define EPSV 1e-10f

// Scratch for the segment-sum (ptr) buffer: 100000*128 fp32 = 51.2 MB.
// Device-global array (no allocation allowed in kernel_launch).
__device__ float g_ptr[(size_t)NN * CC];

// ---------------------------------------------------------------------------
// Kernel 1: zero the segment-sum scratch (float4 stores, grid-stride)
// ---------------------------------------------------------------------------
__global__ void zero_kernel() {
    float4* p = reinterpret_cast<float4*>(g_ptr);
    const int n4 = NN * CC / 4;
    for (int i = blockIdx.x * blockDim.x + threadIdx.x; i < n4;
         i += gridDim.x * blockDim.x) {
        p[i] = make_float4(0.f, 0.f, 0.f, 0.f);
    }
}

// ---------------------------------------------------------------------------
// Kernel 2: scatter. One warp per edge.
//   message[e] = emb[sidx[e]] * norm[e];  ptr[tidx[e]] += message[e]
// Each lane handles 4 channels via float4 load + red.global.add.v4.f32
// (vectorized no-return atomic, sm_90+): 1 REDG op per 16 bytes.
// ---------------------------------------------------------------------------
__global__ void scatter_kernel(const float* __restrict__ emb,
                               const int*   __restrict__ ei,
                               const float* __restrict__ en) {
    const int warp = (blockIdx.x * blockDim.x + threadIdx.x) >> 5;
    if (warp >= EE) return;
    const int lane = threadIdx.x & 31;

    const int   s   = __ldg(ei + warp);        // source node
    const int   t   = __ldg(ei + EE + warp);   // target node
    const float nrm = __ldg(en + warp);

    float4 v = *reinterpret_cast<const float4*>(emb + (size_t)s * CC + lane * 4);
    v.x *= nrm; v.y *= nrm; v.z *= nrm; v.w *= nrm;

    float* dst = g_ptr + (size_t)t * CC + lane * 4;
    asm volatile("red.global.add.v4.f32 [%0], {%1, %2, %3, %4};"
                 :: "l"(dst), "f"(v.x), "f"(v.y), "f"(v.z), "f"(v.w)
                 : "memory");
}

// ---------------------------------------------------------------------------
// Kernel 3: fused dual GEMM + bias + softplus epilogue.
//   loc = ptr @ loc_w.T + loc_b
//   std = softplus(ptr @ std_w.T + std_b) + EPS
// Block: 256 threads. Threads [0,128) compute loc channel j=tid,
// threads [128,256) compute std channel j=tid-128. Both W^T matrices live in
// smem with stride 129 (conflict-free: lane j reads wt[k*129+j]).
// 8-row register blocking: each inner k-iteration does 1 weight LDS +
// 8 broadcast LDS + 8 FMAs per thread.
// ---------------------------------------------------------------------------
#define ROWS_PER_BLOCK 128
#define ROW_CHUNK 8
#define WSTRIDE 129

extern __shared__ float s_mem[];

__global__ __launch_bounds__(256, 1)
void gemm_kernel(const float* __restrict__ lw, const float* __restrict__ lb,
                 const float* __restrict__ sw, const float* __restrict__ sb,
                 float* __restrict__ out) {
    float* wl = s_mem;                         // 128*129 floats
    float* ws = s_mem + CC * WSTRIDE;          // 128*129 floats
    float* pt = s_mem + 2 * CC * WSTRIDE;      // 8*128 floats (row tile)

    const int tid = threadIdx.x;

    // Load both weight matrices transposed into smem: wt[k*129 + j] = W[j][k]
    for (int idx = tid; idx < CC * CC; idx += 256) {
        const int j = idx >> 7;
        const int k = idx & (CC - 1);
        wl[k * WSTRIDE + j] = lw[idx];
        ws[k * WSTRIDE + j] = sw[idx];
    }

    const int half = tid >> 7;          // 0 = loc, 1 = std
    const int j    = tid & (CC - 1);
    const float* wt   = half ? ws : wl;
    const float  bias = half ? __ldg(sb + j) : __ldg(lb + j);
    float* obase = out + (half ? (size_t)NN * CC : (size_t)0);

    const int row0 = blockIdx.x * ROWS_PER_BLOCK;
    __syncthreads();

    for (int c = 0; c < ROWS_PER_BLOCK; c += ROW_CHUNK) {
        const int rbase = row0 + c;
        if (rbase >= NN) break;
        const int nrows = min(ROW_CHUNK, NN - rbase);

        __syncthreads();  // previous chunk's readers done before overwriting pt
        for (int idx = tid; idx < nrows * CC; idx += 256)
            pt[idx] = g_ptr[(size_t)rbase * CC + idx];
        __syncthreads();

        float acc[ROW_CHUNK];
#pragma unroll
        for (int r = 0; r < ROW_CHUNK; r++) acc[r] = 0.f;

#pragma unroll 4
        for (int k = 0; k < CC; k++) {
            const float w = wt[k * WSTRIDE + j];
#pragma unroll
            for (int r = 0; r < ROW_CHUNK; r++)
                acc[r] += pt[r * CC + k] * w;
        }

        for (int r = 0; r < nrows; r++) {
            float x = acc[r] + bias;
            if (half) {
                // numerically stable softplus
                float sp = (x > 0.f) ? (x + log1pf(__expf(-x)))
                                     : log1pf(__expf(x));
                x = sp + EPSV;
            }
            obase[(size_t)(rbase + r) * CC + j] = x;
        }
    }
}

// ---------------------------------------------------------------------------
// Launch. Inputs (metadata order): emb, loc_w, loc_b, std_w, std_b,
//                                  edge_index, edge_norm
// Output: [loc (N*C) | std (N*C)] fp32
// ---------------------------------------------------------------------------
extern "C" void kernel_launch(void* const* d_in, const int* in_sizes, int n_in,
                              void* d_out, int out_size) {
    const float* emb = (const float*)d_in[0];
    const float* lw  = (const float*)d_in[1];
    const float* lb  = (const float*)d_in[2];
    const float* sw  = (const float*)d_in[3];
    const float* sb  = (const float*)d_in[4];
    const int*   ei  = (const int*)  d_in[5];
    const float* en  = (const float*)d_in[6];
    float* out = (float*)d_out;

    zero_kernel<<<1184, 256>>>();

    // one warp per edge: EE warps, 8 warps/block
    const int sblocks = (EE + 7) / 8;
    scatter_kernel<<<sblocks, 256>>>(emb, ei, en);

    const int smem_bytes = (2 * CC * WSTRIDE + ROW_CHUNK * CC) * (int)sizeof(float);
    cudaFuncSetAttribute(gemm_kernel,
                         cudaFuncAttributeMaxDynamicSharedMemorySize, smem_bytes);
    const int gblocks = (NN + ROWS_PER_BLOCK - 1) / ROWS_PER_BLOCK;
    gemm_kernel<<<gblocks, 256, smem_bytes>>>(lw, lb, sw, sb, out);
}

// round 2
// speedup vs baseline: 2.0106x; 2.0106x over previous
#include <cuda_runtime.h>
#include <math.h>

#define NN 100000
#define CC 128
#define EE 600000
#define EPSV 1e-10f

#define RT 64                          // rows per GEMM tile
#define NTILES ((NN + RT - 1) / RT)    // 1563
#define GBLK 148                       // persistent blocks (1/SM)

typedef unsigned long long u64;

// Scratch for the segment-sum (ptr) buffer: 100000*128 fp32 = 51.2 MB.
__device__ float g_ptr[(size_t)NN * CC];

// ---------------------------------------------------------------------------
// packed f32x2 helpers (sm_100+; ptxas never emits FFMA2 from C++)
// ---------------------------------------------------------------------------
__device__ __forceinline__ u64 ffma2(u64 a, u64 b, u64 c) {
    u64 d;
    asm("fma.rn.f32x2 %0, %1, %2, %3;" : "=l"(d) : "l"(a), "l"(b), "l"(c));
    return d;
}
__device__ __forceinline__ u64 pack2(float lo, float hi) {
    u64 d;
    asm("mov.b64 %0, {%1, %2};" : "=l"(d) : "f"(lo), "f"(hi));
    return d;
}
__device__ __forceinline__ void unpack2(u64 d, float& lo, float& hi) {
    asm("mov.b64 {%0, %1}, %2;" : "=f"(lo), "=f"(hi) : "l"(d));
}

// ---------------------------------------------------------------------------
// Kernel 1: zero the segment-sum scratch (L2-resident, ~10us)
// ---------------------------------------------------------------------------
__global__ void zero_kernel() {
    float4* p = reinterpret_cast<float4*>(g_ptr);
    const int n4 = NN * CC / 4;
    for (int i = blockIdx.x * blockDim.x + threadIdx.x; i < n4;
         i += gridDim.x * blockDim.x) {
        p[i] = make_float4(0.f, 0.f, 0.f, 0.f);
    }
}

// ---------------------------------------------------------------------------
// Kernel 2: scatter. One warp per edge, red.global.add.v4.f32 (no-return
// vectorized atomic). L2-throughput-bound.
// ---------------------------------------------------------------------------
__global__ void scatter_kernel(const float* __restrict__ emb,
                               const int*   __restrict__ ei,
                               const float* __restrict__ en) {
    const int warp = (blockIdx.x * blockDim.x + threadIdx.x) >> 5;
    if (warp >= EE) return;
    const int lane = threadIdx.x & 31;

    const int   s   = __ldg(ei + warp);        // source node
    const int   t   = __ldg(ei + EE + warp);   // target node
    const float nrm = __ldg(en + warp);

    float4 v = *reinterpret_cast<const float4*>(emb + (size_t)s * CC + lane * 4);
    v.x *= nrm; v.y *= nrm; v.z *= nrm; v.w *= nrm;

    float* dst = g_ptr + (size_t)t * CC + lane * 4;
    asm volatile("red.global.add.v4.f32 [%0], {%1, %2, %3, %4};"
                 :: "l"(dst), "f"(v.x), "f"(v.y), "f"(v.z), "f"(v.w)
                 : "memory");
}

// ---------------------------------------------------------------------------
// Kernel 3: persistent fused dual GEMM + bias + softplus, FFMA2-based.
//   out[0:N)    = ptr @ loc_w.T + loc_b
//   out[N:2N)   = softplus(ptr @ std_w.T + std_b) + EPS
//
// Combined output channels jc in [0,256): jc<128 -> loc, else std.
// smem:
//   wt   [k][pid]  f32x2 pair (cols 2*pid, 2*pid+1) of combined W : 128 KB
//   pt2  [r][k]    row value duplicated (v,v)                     :  64 KB
//   bias [pid]     f32x2                                          :   1 KB
// Thread (c = tid&31, rg = tid>>5): 8 rows (rg*8..) x 4 pairs (p*32+c).
// Per k-step: 4 LDS.64 (wt, conflict-free) + 8 LDS.64 (pt2 broadcast)
//             + 32 FFMA2  -> FMA-pipe / LDS co-limited at ~128 lanes/cyc/SM.
// ---------------------------------------------------------------------------
__global__ __launch_bounds__(256, 1)
void gemm_kernel(const float* __restrict__ lw, const float* __restrict__ lb,
                 const float* __restrict__ sw, const float* __restrict__ sb,
                 float* __restrict__ out) {
    extern __shared__ u64 smem[];
    u64* wt    = smem;                 // 128*128 pairs
    u64* pt2   = wt + CC * CC;         // RT*128 duplicated row values
    u64* sbias = pt2 + RT * CC;        // 128 pairs

    const int tid = threadIdx.x;

    // ---- load combined weights, paired along output channel ----
    // wt[k*128 + pid] = ( Wc[2*pid][k], Wc[2*pid+1][k] )
    for (int idx = tid; idx < CC * CC; idx += 256) {
        const int pid = idx >> 7;      // pair id 0..127
        const int k   = idx & (CC - 1);
        const int jc0 = pid * 2;
        float a, b;
        if (jc0 < CC) { a = lw[jc0 * CC + k];        b = lw[(jc0 + 1) * CC + k]; }
        else          { a = sw[(jc0 - CC) * CC + k]; b = sw[(jc0 + 1 - CC) * CC + k]; }
        wt[k * CC + pid] = pack2(a, b);
    }
    if (tid < CC) {
        const int jc0 = tid * 2;
        float a, b;
        if (jc0 < CC) { a = lb[jc0];      b = lb[jc0 + 1]; }
        else          { a = sb[jc0 - CC]; b = sb[jc0 + 1 - CC]; }
        sbias[tid] = pack2(a, b);
    }

    const int c  = tid & 31;           // pair-group lane
    const int rg = tid >> 5;           // row group 0..7

    for (int tile = blockIdx.x; tile < NTILES; tile += gridDim.x) {
        const int row0 = tile * RT;

        __syncthreads();  // prior compute done (and weight fill on iter 0)
        // ---- fill duplicated row tile ----
        for (int idx = tid; idx < RT * CC / 4; idx += 256) {
            const int fidx = idx * 4;
            const int row  = fidx >> 7;
            const int k    = fidx & (CC - 1);
            float4 v;
            if (row0 + row < NN)
                v = *reinterpret_cast<const float4*>(g_ptr + (size_t)(row0 + row) * CC + k);
            else
                v = make_float4(0.f, 0.f, 0.f, 0.f);
            u64* dst = pt2 + row * CC + k;
            dst[0] = pack2(v.x, v.x);
            dst[1] = pack2(v.y, v.y);
            dst[2] = pack2(v.z, v.z);
            dst[3] = pack2(v.w, v.w);
        }
        __syncthreads();

        u64 acc[8][4];
#pragma unroll
        for (int r = 0; r < 8; r++)
#pragma unroll
            for (int p = 0; p < 4; p++) acc[r][p] = 0ull;  // bits of (0.f,0.f)

#pragma unroll 4
        for (int k = 0; k < CC; k++) {
            const u64 w0 = wt[k * CC +  0 + c];
            const u64 w1 = wt[k * CC + 32 + c];
            const u64 w2 = wt[k * CC + 64 + c];
            const u64 w3 = wt[k * CC + 96 + c];
#pragma unroll
            for (int r = 0; r < 8; r++) {
                const u64 rv = pt2[(rg * 8 + r) * CC + k];  // broadcast
                acc[r][0] = ffma2(rv, w0, acc[r][0]);
                acc[r][1] = ffma2(rv, w1, acc[r][1]);
                acc[r][2] = ffma2(rv, w2, acc[r][2]);
                acc[r][3] = ffma2(rv, w3, acc[r][3]);
            }
        }

        // ---- epilogue: bias, softplus for std half, float2 stores ----
#pragma unroll
        for (int p = 0; p < 4; p++) {
            const int pid = p * 32 + c;
            const int jc0 = pid * 2;
            float b0, b1;
            unpack2(sbias[pid], b0, b1);
            const bool is_std = (jc0 >= CC);
#pragma unroll
            for (int r = 0; r < 8; r++) {
                const int row = row0 + rg * 8 + r;
                if (row >= NN) break;
                float x0, x1;
                unpack2(acc[r][p], x0, x1);
                x0 += b0; x1 += b1;
                float* dst;
                if (is_std) {
                    x0 = ((x0 > 0.f) ? (x0 + log1pf(__expf(-x0))) : log1pf(__expf(x0))) + EPSV;
                    x1 = ((x1 > 0.f) ? (x1 + log1pf(__expf(-x1))) : log1pf(__expf(x1))) + EPSV;
                    dst = out + (size_t)NN * CC + (size_t)row * CC + (jc0 - CC);
                } else {
                    dst = out + (size_t)row * CC + jc0;
                }
                *reinterpret_cast<float2*>(dst) = make_float2(x0, x1);
            }
        }
    }
}

// ---------------------------------------------------------------------------
// Launch. Inputs: emb, loc_w, loc_b, std_w, std_b, edge_index, edge_norm
// Output: [loc (N*C) | std (N*C)] fp32
// ---------------------------------------------------------------------------
extern "C" void kernel_launch(void* const* d_in, const int* in_sizes, int n_in,
                              void* d_out, int out_size) {
    const float* emb = (const float*)d_in[0];
    const float* lw  = (const float*)d_in[1];
    const float* lb  = (const float*)d_in[2];
    const float* sw  = (const float*)d_in[3];
    const float* sb  = (const float*)d_in[4];
    const int*   ei  = (const int*)  d_in[5];
    const float* en  = (const float*)d_in[6];
    float* out = (float*)d_out;

    zero_kernel<<<1184, 256>>>();

    const int sblocks = (EE + 7) / 8;  // one warp per edge
    scatter_kernel<<<sblocks, 256>>>(emb, ei, en);

    const int smem_bytes = (CC * CC + RT * CC + CC) * (int)sizeof(u64);  // 197,632 B
    static int smem_set = 0;
    if (!smem_set) {
        cudaFuncSetAttribute(gemm_kernel,
                             cudaFuncAttributeMaxDynamicSharedMemorySize, smem_bytes);
        smem_set = 1;
    }
    gemm_kernel<<<GBLK, 256, smem_bytes>>>(lw, lb, sw, sb, out);
}

// round 3
// speedup vs baseline: 2.1395x; 1.0641x over previous
#include <cuda_runtime.h>
#include <math.h>

#define NN 100000
#define CC 128
#define EE 600000
#define EPSV 1e-10f

#define RT 64                          // rows per GEMM tile
#define NTILES ((NN + RT - 1) / RT)    // 1563
#define GBLK 148                       // persistent blocks (1/SM)

#define SCAN_B 1024
#define SCAN_NBLK ((NN + SCAN_B - 1) / SCAN_B)   // 98

typedef unsigned long long u64;
typedef unsigned int u32;

// ---------------------------------------------------------------------------
// Device scratch (no allocation allowed in kernel_launch)
// ---------------------------------------------------------------------------
__device__ float g_ptr[(size_t)NN * CC];   // segment-sum result, 51.2 MB
__device__ int   g_cnt[NN];                // per-node edge count
__device__ int   g_scan[NN];               // block-inclusive scan of counts
__device__ int   g_rowstart[NN];           // CSR row start (exclusive scan)
__device__ int   g_cursor[NN];             // write cursor for permutation
__device__ int   g_bsums[SCAN_NBLK];       // per-scan-block totals
__device__ u64   g_edges[EE];              // packed (norm:f32 << 32 | src:u32)

// ---------------------------------------------------------------------------
// packed f32x2 helpers (sm_100+; ptxas never emits FFMA2 from C++)
// ---------------------------------------------------------------------------
__device__ __forceinline__ u64 ffma2(u64 a, u64 b, u64 c) {
    u64 d;
    asm("fma.rn.f32x2 %0, %1, %2, %3;" : "=l"(d) : "l"(a), "l"(b), "l"(c));
    return d;
}
__device__ __forceinline__ u64 pack2(float lo, float hi) {
    u64 d;
    asm("mov.b64 %0, {%1, %2};" : "=l"(d) : "f"(lo), "f"(hi));
    return d;
}
__device__ __forceinline__ void unpack2(u64 d, float& lo, float& hi) {
    asm("mov.b64 {%0, %1}, %2;" : "=f"(lo), "=f"(hi) : "l"(d));
}

// ---------------------------------------------------------------------------
// CSR build: zero counts -> histogram -> scan(x3) -> permute
// ---------------------------------------------------------------------------
__global__ void zero_cnt_kernel() {
    for (int i = blockIdx.x * blockDim.x + threadIdx.x; i < NN;
         i += gridDim.x * blockDim.x)
        g_cnt[i] = 0;
}

__global__ void hist_kernel(const int* __restrict__ ei) {
    for (int e = blockIdx.x * blockDim.x + threadIdx.x; e < EE;
         e += gridDim.x * blockDim.x)
        atomicAdd(&g_cnt[__ldg(ei + EE + e)], 1);
}

__global__ __launch_bounds__(SCAN_B)
void scan_block_kernel() {
    __shared__ int wsum[32];
    const int tid  = threadIdx.x;
    const int gi   = blockIdx.x * SCAN_B + tid;
    const int lane = tid & 31;
    const int wid  = tid >> 5;

    int v = (gi < NN) ? g_cnt[gi] : 0;
    // warp inclusive scan
    int s = v;
#pragma unroll
    for (int d = 1; d < 32; d <<= 1) {
        int t = __shfl_up_sync(0xffffffffu, s, d);
        if (lane >= d) s += t;
    }
    if (lane == 31) wsum[wid] = s;
    __syncthreads();
    if (wid == 0) {
        int w = wsum[lane];
        int ws = w;
#pragma unroll
        for (int d = 1; d < 32; d <<= 1) {
            int t = __shfl_up_sync(0xffffffffu, ws, d);
            if (lane >= d) ws += t;
        }
        wsum[lane] = ws - w;   // exclusive warp offsets
    }
    __syncthreads();
    const int incl = s + wsum[wid];
    if (gi < NN) g_scan[gi] = incl;
    if (tid == SCAN_B - 1) g_bsums[blockIdx.x] = incl;
}

__global__ void scan_sums_kernel() {
    if (threadIdx.x == 0 && blockIdx.x == 0) {
        int run = 0;
        for (int b = 0; b < SCAN_NBLK; b++) {
            int t = g_bsums[b];
            g_bsums[b] = run;
            run += t;
        }
    }
}

__global__ void finalize_scan_kernel() {
    for (int i = blockIdx.x * blockDim.x + threadIdx.x; i < NN;
         i += gridDim.x * blockDim.x) {
        const int rs = g_scan[i] - g_cnt[i] + g_bsums[i / SCAN_B];
        g_rowstart[i] = rs;
        g_cursor[i]   = rs;
    }
}

__global__ void permute_kernel(const int* __restrict__ ei,
                               const float* __restrict__ en) {
    for (int e = blockIdx.x * blockDim.x + threadIdx.x; e < EE;
         e += gridDim.x * blockDim.x) {
        const int   s = __ldg(ei + e);
        const int   t = __ldg(ei + EE + e);
        const float n = __ldg(en + e);
        const int   p = atomicAdd(&g_cursor[t], 1);
        g_edges[p] = ((u64)__float_as_uint(n) << 32) | (u32)s;
    }
}

// ---------------------------------------------------------------------------
// Aggregation: one warp per node. Gather emb rows of its (contiguous) edges,
// accumulate in registers, single float4 store per node. No float atomics,
// no zero pass.
// ---------------------------------------------------------------------------
__global__ __launch_bounds__(256)
void aggregate_kernel(const float* __restrict__ emb) {
    const int node = (blockIdx.x * blockDim.x + threadIdx.x) >> 5;
    if (node >= NN) return;
    const int lane = threadIdx.x & 31;

    const int beg = g_rowstart[node];
    const int cnt = g_cnt[node];

    float4 a = make_float4(0.f, 0.f, 0.f, 0.f);
#pragma unroll 2
    for (int i = 0; i < cnt; i++) {
        const u64  rec = __ldg(&g_edges[beg + i]);
        const int  s   = (int)(u32)rec;
        const float nm = __uint_as_float((u32)(rec >> 32));
        const float4 v = *reinterpret_cast<const float4*>(
            emb + (size_t)s * CC + lane * 4);
        a.x += v.x * nm; a.y += v.y * nm; a.z += v.z * nm; a.w += v.w * nm;
    }
    *reinterpret_cast<float4*>(g_ptr + (size_t)node * CC + lane * 4) = a;
}

// ---------------------------------------------------------------------------
// Persistent fused dual GEMM + bias + softplus, FFMA2-based (unchanged).
// ---------------------------------------------------------------------------
__global__ __launch_bounds__(256, 1)
void gemm_kernel(const float* __restrict__ lw, const float* __restrict__ lb,
                 const float* __restrict__ sw, const float* __restrict__ sb,
                 float* __restrict__ out) {
    extern __shared__ u64 smem[];
    u64* wt    = smem;                 // 128*128 pairs
    u64* pt2   = wt + CC * CC;         // RT*128 duplicated row values
    u64* sbias = pt2 + RT * CC;        // 128 pairs

    const int tid = threadIdx.x;

    for (int idx = tid; idx < CC * CC; idx += 256) {
        const int pid = idx >> 7;
        const int k   = idx & (CC - 1);
        const int jc0 = pid * 2;
        float a, b;
        if (jc0 < CC) { a = lw[jc0 * CC + k];        b = lw[(jc0 + 1) * CC + k]; }
        else          { a = sw[(jc0 - CC) * CC + k]; b = sw[(jc0 + 1 - CC) * CC + k]; }
        wt[k * CC + pid] = pack2(a, b);
    }
    if (tid < CC) {
        const int jc0 = tid * 2;
        float a, b;
        if (jc0 < CC) { a = lb[jc0];      b = lb[jc0 + 1]; }
        else          { a = sb[jc0 - CC]; b = sb[jc0 + 1 - CC]; }
        sbias[tid] = pack2(a, b);
    }

    const int c  = tid & 31;
    const int rg = tid >> 5;

    for (int tile = blockIdx.x; tile < NTILES; tile += gridDim.x) {
        const int row0 = tile * RT;

        __syncthreads();
        for (int idx = tid; idx < RT * CC / 4; idx += 256) {
            const int fidx = idx * 4;
            const int row  = fidx >> 7;
            const int k    = fidx & (CC - 1);
            float4 v;
            if (row0 + row < NN)
                v = *reinterpret_cast<const float4*>(g_ptr + (size_t)(row0 + row) * CC + k);
            else
                v = make_float4(0.f, 0.f, 0.f, 0.f);
            u64* dst = pt2 + row * CC + k;
            dst[0] = pack2(v.x, v.x);
            dst[1] = pack2(v.y, v.y);
            dst[2] = pack2(v.z, v.z);
            dst[3] = pack2(v.w, v.w);
        }
        __syncthreads();

        u64 acc[8][4];
#pragma unroll
        for (int r = 0; r < 8; r++)
#pragma unroll
            for (int p = 0; p < 4; p++) acc[r][p] = 0ull;

#pragma unroll 4
        for (int k = 0; k < CC; k++) {
            const u64 w0 = wt[k * CC +  0 + c];
            const u64 w1 = wt[k * CC + 32 + c];
            const u64 w2 = wt[k * CC + 64 + c];
            const u64 w3 = wt[k * CC + 96 + c];
#pragma unroll
            for (int r = 0; r < 8; r++) {
                const u64 rv = pt2[(rg * 8 + r) * CC + k];
                acc[r][0] = ffma2(rv, w0, acc[r][0]);
                acc[r][1] = ffma2(rv, w1, acc[r][1]);
                acc[r][2] = ffma2(rv, w2, acc[r][2]);
                acc[r][3] = ffma2(rv, w3, acc[r][3]);
            }
        }

#pragma unroll
        for (int p = 0; p < 4; p++) {
            const int pid = p * 32 + c;
            const int jc0 = pid * 2;
            float b0, b1;
            unpack2(sbias[pid], b0, b1);
            const bool is_std = (jc0 >= CC);
#pragma unroll
            for (int r = 0; r < 8; r++) {
                const int row = row0 + rg * 8 + r;
                if (row >= NN) break;
                float x0, x1;
                unpack2(acc[r][p], x0, x1);
                x0 += b0; x1 += b1;
                float* dst;
                if (is_std) {
                    x0 = ((x0 > 0.f) ? (x0 + log1pf(__expf(-x0))) : log1pf(__expf(x0))) + EPSV;
                    x1 = ((x1 > 0.f) ? (x1 + log1pf(__expf(-x1))) : log1pf(__expf(x1))) + EPSV;
                    dst = out + (size_t)NN * CC + (size_t)row * CC + (jc0 - CC);
                } else {
                    dst = out + (size_t)row * CC + jc0;
                }
                *reinterpret_cast<float2*>(dst) = make_float2(x0, x1);
            }
        }
    }
}

// ---------------------------------------------------------------------------
// Launch. Inputs: emb, loc_w, loc_b, std_w, std_b, edge_index, edge_norm
// ---------------------------------------------------------------------------
extern "C" void kernel_launch(void* const* d_in, const int* in_sizes, int n_in,
                              void* d_out, int out_size) {
    const float* emb = (const float*)d_in[0];
    const float* lw  = (const float*)d_in[1];
    const float* lb  = (const float*)d_in[2];
    const float* sw  = (const float*)d_in[3];
    const float* sb  = (const float*)d_in[4];
    const int*   ei  = (const int*)  d_in[5];
    const float* en  = (const float*)d_in[6];
    float* out = (float*)d_out;

    zero_cnt_kernel<<<391, 256>>>();
    hist_kernel<<<1184, 256>>>(ei);
    scan_block_kernel<<<SCAN_NBLK, SCAN_B>>>();
    scan_sums_kernel<<<1, 32>>>();
    finalize_scan_kernel<<<391, 256>>>();
    permute_kernel<<<1184, 256>>>(ei, en);

    aggregate_kernel<<<(NN * 32 + 255) / 256, 256>>>(emb);

    const int smem_bytes = (CC * CC + RT * CC + CC) * (int)sizeof(u64);
    static int smem_set = 0;
    if (!smem_set) {
        cudaFuncSetAttribute(gemm_kernel,
                             cudaFuncAttributeMaxDynamicSharedMemorySize, smem_bytes);
        smem_set = 1;
    }
    gemm_kernel<<<GBLK, 256, smem_bytes>>>(lw, lb, sw, sb, out);
}